// round 8
// baseline (speedup 1.0000x reference)
#include <cuda_runtime.h>
#include <cuda_fp16.h>
#include <cuda_bf16.h>

#define NN 100000
#define NE 1600000
#define NG 512
#define H1C 64
#define H2C 128
#define OUTC 2
#define NBS 98          // ceil(NN / 1024) scan blocks

// ---------------- scratch (__device__ globals) ----------------
__device__ __align__(16) int     g_icnt[NN];        // in-degree
__device__ __align__(16) int     g_off [NN];        // CSR exclusive offsets
__device__ __align__(16) int     g_cur [NN];        // scatter cursors
__device__ __align__(16) int     g_bsum[128];       // scan block sums
__device__ __align__(16) int     g_csrc[NE];        // CSR: src per slot
__device__ __align__(16) float   g_dinv[NN];
__device__ __align__(16) float   g_xs4 [NN * 4];    // {d*x0, d*x1, d*x2, d}
__device__ __align__(16) __half2 g_h1h [NN * 32];   // fp16 dinv-scaled relu(layer1)
__device__ __align__(16) __half2 g_aggh2[NN * 32];  // fp16 layer-2 aggregate
__device__ __align__(16) float   g_pool[NG * H2C];
__device__ __align__(16) float   g_cnt [NG];

__device__ __forceinline__ void red_add_f(float* addr, float v) {
    asm volatile("red.global.add.f32 [%0], %1;" :: "l"(addr), "f"(v) : "memory");
}

// -------------------------------- zero in-degree counters
__global__ void k_zero() {
    int i = blockIdx.x * blockDim.x + threadIdx.x;
    if (i < NN / 4) ((int4*)g_icnt)[i] = make_int4(0, 0, 0, 0);
}

// -------------------------------- in-degree count
__global__ void k_count(const int* __restrict__ dst) {
    int e = blockIdx.x * blockDim.x + threadIdx.x;
    if (e < NE) atomicAdd(&g_icnt[dst[e]], 1);
}

// -------------------------------- scan pass 1: per-1024 chunks
__global__ void __launch_bounds__(256) k_scan1() {
    __shared__ int sh[256];
    int base = blockIdx.x * 1024;
    int t = threadIdx.x;
    int v[4], s = 0;
#pragma unroll
    for (int j = 0; j < 4; j++) {
        int idx = base + t * 4 + j;
        v[j] = (idx < NN) ? g_icnt[idx] : 0;
        s += v[j];
    }
    sh[t] = s;
    __syncthreads();
    for (int o = 1; o < 256; o <<= 1) {
        int x = (t >= o) ? sh[t - o] : 0;
        __syncthreads();
        sh[t] += x;
        __syncthreads();
    }
    int run = sh[t] - s;
#pragma unroll
    for (int j = 0; j < 4; j++) {
        int idx = base + t * 4 + j;
        if (idx < NN) g_off[idx] = run;
        run += v[j];
    }
    if (t == 255) g_bsum[blockIdx.x] = sh[255];
}

// ------ scan pass 2+3 merged: each block reduces its chunk prefix itself,
//        finalizes offsets/cursors, computes dinv & xs4, zeroes pool/cnt.
__global__ void __launch_bounds__(256) k_scan23(const float* __restrict__ x) {
    __shared__ int red[256];
    int t = threadIdx.x;
    int chunk = blockIdx.x >> 2;           // 4 blocks of 256 per 1024-chunk
    int part = 0;
    for (int j = t; j < chunk; j += 256) part += g_bsum[j];
    red[t] = part;
    __syncthreads();
    for (int o = 128; o; o >>= 1) {
        if (t < o) red[t] += red[t + o];
        __syncthreads();
    }
    int pref = red[0];

    int i = blockIdx.x * 256 + t;
    if (i < NN) {
        int o = g_off[i] + pref;
        g_off[i] = o;
        g_cur[i] = o;
        float d = rsqrtf((float)g_icnt[i] + 1.0f);
        g_dinv[i] = d;
        ((float4*)g_xs4)[i] =
            make_float4(d * x[i * 3 + 0], d * x[i * 3 + 1], d * x[i * 3 + 2], d);
    }
    if (i < NG * H2C) g_pool[i] = 0.f;
    if (i < NG)       g_cnt[i]  = 0.f;
}

// -------------------------------- CSR fill
__global__ void k_fill(const int* __restrict__ src, const int* __restrict__ dst) {
    int e = blockIdx.x * blockDim.x + threadIdx.x;
    if (e >= NE) return;
    int d = dst[e];
    int pos = atomicAdd(&g_cur[d], 1);
    g_csrc[pos] = src[e];
}

// ------- layer 1 fused gather + dense (warp per node), fp16 output
__global__ void __launch_bounds__(128) k_l1g(const float* __restrict__ W1,
                                             const float* __restrict__ b1) {
    int warp = threadIdx.x >> 5;
    int lane = threadIdx.x & 31;
    int node = blockIdx.x * 4 + warp;
    if (node >= NN) return;

    int beg = g_off[node];
    int cnt = g_icnt[node];
    float sx = 0.f, sy = 0.f, sz = 0.f;
    for (int j = lane; j < cnt; j += 32) {
        int s = g_csrc[beg + j];
        float4 v = ((const float4*)g_xs4)[s];
        sx += v.x; sy += v.y; sz += v.z;
    }
#pragma unroll
    for (int o = 16; o; o >>= 1) {
        sx += __shfl_xor_sync(0xffffffffu, sx, o);
        sy += __shfl_xor_sync(0xffffffffu, sy, o);
        sz += __shfl_xor_sync(0xffffffffu, sz, o);
    }
    float4 self = ((const float4*)g_xs4)[node];
    float d = self.w;
    float a0 = d * (sx + self.x);
    float a1 = d * (sy + self.y);
    float a2 = d * (sz + self.z);

    int f = lane * 2;
    float v0 = a0 * __ldg(&W1[f])       + a1 * __ldg(&W1[64 + f])
             + a2 * __ldg(&W1[128 + f])   + __ldg(&b1[f]);
    float v1 = a0 * __ldg(&W1[f + 1])   + a1 * __ldg(&W1[64 + f + 1])
             + a2 * __ldg(&W1[128 + f + 1]) + __ldg(&b1[f + 1]);
    g_h1h[node * 32 + lane] =
        __floats2half2_rn(d * fmaxf(v0, 0.f), d * fmaxf(v1, 0.f));
}

// ------- layer 2 edge aggregation via CSR (warp per node, fp32 acc, half2 out)
__global__ void __launch_bounds__(128) k_eh() {
    int warp = threadIdx.x >> 5;
    int lane = threadIdx.x & 31;
    int node = blockIdx.x * 4 + warp;
    if (node >= NN) return;

    int beg = g_off[node];
    int cnt = g_icnt[node];
    const __half2* H = g_h1h;

    float2 accA = __half22float2(H[node * 32 + lane]);  // self term
    float2 accB = make_float2(0.f, 0.f);

    int j = 0;
#pragma unroll 2
    for (; j + 2 <= cnt; j += 2) {
        int s0 = g_csrc[beg + j];
        int s1 = g_csrc[beg + j + 1];
        float2 v0 = __half22float2(H[s0 * 32 + lane]);
        float2 v1 = __half22float2(H[s1 * 32 + lane]);
        accA.x += v0.x; accA.y += v0.y;
        accB.x += v1.x; accB.y += v1.y;
    }
    if (j < cnt) {
        int s = g_csrc[beg + j];
        float2 v = __half22float2(H[s * 32 + lane]);
        accA.x += v.x; accA.y += v.y;
    }
    float d = g_dinv[node];
    g_aggh2[node * 32 + lane] =
        __floats2half2_rn(d * (accA.x + accB.x), d * (accA.y + accB.y));
}

// ---- layer-2 dense via tensor cores + fused mean-pool
// 3 warps/block, warp = 16-node tile. A = agg (fp16), B = W2 (fp16), C fp32.
#define L2PAD 130
__global__ void __launch_bounds__(96)
k_l2t(const float* __restrict__ W2, const float* __restrict__ b2,
      const int* __restrict__ batch) {
    __shared__ __half2 sB[128 * 33];          // W2 fragments: pair(k,k+1) per col
    __shared__ float   sC[3][16 * L2PAD];     // per-warp C staging

    int tid = threadIdx.x;
    for (int idx = tid; idx < 128 * 32; idx += 96) {
        int n = idx >> 5, k2 = idx & 31;
        sB[n * 33 + k2] =
            __floats2half2_rn(W2[(2 * k2) * H2C + n], W2[(2 * k2 + 1) * H2C + n]);
    }
    __syncthreads();

    int warp = tid >> 5, lane = tid & 31;
    int tile = blockIdx.x * 3 + warp;
    int node0 = tile * 16;
    if (node0 >= NN) return;
    int g = lane >> 2, t = lane & 3;

    // A fragments: 4 k-steps × 4 b32 regs
    unsigned a[4][4];
    {
        const unsigned* A = (const unsigned*)g_aggh2;
        int r0 = (node0 + g) * 32, r1 = (node0 + g + 8) * 32;
#pragma unroll
        for (int kk = 0; kk < 4; kk++) {
            a[kk][0] = A[r0 + kk * 8 + t];
            a[kk][1] = A[r1 + kk * 8 + t];
            a[kk][2] = A[r0 + kk * 8 + t + 4];
            a[kk][3] = A[r1 + kk * 8 + t + 4];
        }
    }

    float* myC = sC[warp];
#pragma unroll
    for (int nt = 0; nt < 16; nt++) {
        float c0 = 0.f, c1 = 0.f, c2 = 0.f, c3 = 0.f;
        int n = nt * 8 + g;
#pragma unroll
        for (int kk = 0; kk < 4; kk++) {
            unsigned b0 = *(const unsigned*)&sB[n * 33 + kk * 8 + t];
            unsigned b1 = *(const unsigned*)&sB[n * 33 + kk * 8 + t + 4];
            asm volatile(
                "mma.sync.aligned.m16n8k16.row.col.f32.f16.f16.f32 "
                "{%0,%1,%2,%3}, {%4,%5,%6,%7}, {%8,%9}, {%0,%1,%2,%3};"
                : "+f"(c0), "+f"(c1), "+f"(c2), "+f"(c3)
                : "r"(a[kk][0]), "r"(a[kk][1]), "r"(a[kk][2]), "r"(a[kk][3]),
                  "r"(b0), "r"(b1));
        }
        int col = nt * 8 + t * 2;
        *(float2*)&myC[g * L2PAD + col]       = make_float2(c0, c1);
        *(float2*)&myC[(g + 8) * L2PAD + col] = make_float2(c2, c3);
    }
    __syncwarp();

    // pooling epilogue: lane owns cols {lane, +32, +64, +96}; run-flush on batch
    float bias0 = __ldg(&b2[lane]);
    float bias1 = __ldg(&b2[lane + 32]);
    float bias2 = __ldg(&b2[lane + 64]);
    float bias3 = __ldg(&b2[lane + 96]);
    float p0 = 0.f, p1 = 0.f, p2 = 0.f, p3 = 0.f, cntacc = 0.f;
    int cur_g = batch[node0];
#pragma unroll
    for (int r = 0; r < 16; r++) {
        int gid = batch[node0 + r];
        if (gid != cur_g) {
            red_add_f(&g_pool[cur_g * H2C + lane],      p0);
            red_add_f(&g_pool[cur_g * H2C + lane + 32], p1);
            red_add_f(&g_pool[cur_g * H2C + lane + 64], p2);
            red_add_f(&g_pool[cur_g * H2C + lane + 96], p3);
            if (lane == 0) red_add_f(&g_cnt[cur_g], cntacc);
            p0 = p1 = p2 = p3 = 0.f; cntacc = 0.f; cur_g = gid;
        }
        const float* row = &myC[r * L2PAD];
        p0 += fmaxf(row[lane]      + bias0, 0.f);
        p1 += fmaxf(row[lane + 32] + bias1, 0.f);
        p2 += fmaxf(row[lane + 64] + bias2, 0.f);
        p3 += fmaxf(row[lane + 96] + bias3, 0.f);
        cntacc += 1.f;
    }
    red_add_f(&g_pool[cur_g * H2C + lane],      p0);
    red_add_f(&g_pool[cur_g * H2C + lane + 32], p1);
    red_add_f(&g_pool[cur_g * H2C + lane + 64], p2);
    red_add_f(&g_pool[cur_g * H2C + lane + 96], p3);
    if (lane == 0) red_add_f(&g_cnt[cur_g], cntacc);
}

// ---------------------------------------- final: out = (pool/cnt)@Wfc + bfc
__global__ void k_out(const float* __restrict__ Wfc, const float* __restrict__ bfc,
                      float* __restrict__ out) {
    int t = blockIdx.x * blockDim.x + threadIdx.x;
    if (t >= NG * OUTC) return;
    int g = t >> 1, o = t & 1;
    float inv = 1.0f / fmaxf(g_cnt[g], 1.0f);
    float s = 0.f;
#pragma unroll
    for (int k = 0; k < H2C; k++)
        s = fmaf(g_pool[g * H2C + k], __ldg(&Wfc[k * OUTC + o]), s);
    out[t] = s * inv + __ldg(&bfc[o]);
}

extern "C" void kernel_launch(void* const* d_in, const int* in_sizes, int n_in,
                              void* d_out, int out_size) {
    const float* x   = (const float*)d_in[0];
    const int*   ei  = (const int*)d_in[1];   // [2, E] int32
    const int*   bat = (const int*)d_in[2];   // [N] int32
    const float* W1  = (const float*)d_in[3];
    const float* b1  = (const float*)d_in[4];
    const float* W2  = (const float*)d_in[5];
    const float* b2  = (const float*)d_in[6];
    const float* Wfc = (const float*)d_in[7];
    const float* bfc = (const float*)d_in[8];
    float*       out = (float*)d_out;

    const int* src = ei;
    const int* dst = ei + NE;

    const int T = 256;
    k_zero  <<<(NN / 4 + T - 1) / T, T>>>();
    k_count <<<(NE + T - 1) / T, T>>>(dst);
    k_scan1 <<<NBS, 256>>>();
    k_scan23<<<(NN + 255) / 256, 256>>>(x);
    k_fill  <<<(NE + T - 1) / T, T>>>(src, dst);
    k_l1g   <<<NN / 4, 128>>>(W1, b1);
    k_eh    <<<NN / 4, 128>>>();
    k_l2t   <<<(NN / 16 + 2) / 3, 96>>>(W2, b2, bat);
    k_out   <<<(NG * OUTC + T - 1) / T, T>>>(Wfc, bfc, out);
}

// round 9
// speedup vs baseline: 1.4630x; 1.4630x over previous
#include <cuda_runtime.h>
#include <cuda_fp16.h>
#include <cuda_bf16.h>

#define NN 100000
#define NE 1600000
#define NG 512
#define H1C 64
#define H2C 128
#define OUTC 2
#define NBS 98          // ceil(NN / 1024) scan blocks
#define NTILES 6250     // NN / 16

// ---------------- scratch (__device__ globals) ----------------
__device__ __align__(16) int     g_icnt[NN];        // in-degree
__device__ __align__(16) int     g_off [NN];        // CSR exclusive offsets
__device__ __align__(16) int     g_cur [NN];        // scatter cursors
__device__ __align__(16) int     g_bsum[128];       // scan block sums
__device__ __align__(16) int     g_csrc[NE];        // CSR: src per slot
__device__ __align__(16) float   g_dinv[NN];
__device__ __align__(16) float   g_xs4 [NN * 4];    // {d*x0, d*x1, d*x2, d}
__device__ __align__(16) __half2 g_h1h [NN * 32];   // fp16 dinv-scaled relu(layer1)
__device__ __align__(16) __half2 g_aggh2[NN * 32];  // fp16 layer-2 aggregate
__device__ __align__(16) float   g_pool[NG * H2C];
__device__ __align__(16) float   g_cnt [NG];

__device__ __forceinline__ void red_add_f(float* addr, float v) {
    asm volatile("red.global.add.f32 [%0], %1;" :: "l"(addr), "f"(v) : "memory");
}

// -------------------------------- zero in-degree counters
__global__ void k_zero() {
    int i = blockIdx.x * blockDim.x + threadIdx.x;
    if (i < NN / 4) ((int4*)g_icnt)[i] = make_int4(0, 0, 0, 0);
}

// -------------------------------- in-degree count
__global__ void k_count(const int* __restrict__ dst) {
    int e = blockIdx.x * blockDim.x + threadIdx.x;
    if (e < NE) atomicAdd(&g_icnt[dst[e]], 1);
}

// -------------------------------- scan pass 1: per-1024 chunks
__global__ void __launch_bounds__(256) k_scan1() {
    __shared__ int sh[256];
    int base = blockIdx.x * 1024;
    int t = threadIdx.x;
    int v[4], s = 0;
#pragma unroll
    for (int j = 0; j < 4; j++) {
        int idx = base + t * 4 + j;
        v[j] = (idx < NN) ? g_icnt[idx] : 0;
        s += v[j];
    }
    sh[t] = s;
    __syncthreads();
    for (int o = 1; o < 256; o <<= 1) {
        int x = (t >= o) ? sh[t - o] : 0;
        __syncthreads();
        sh[t] += x;
        __syncthreads();
    }
    int run = sh[t] - s;
#pragma unroll
    for (int j = 0; j < 4; j++) {
        int idx = base + t * 4 + j;
        if (idx < NN) g_off[idx] = run;
        run += v[j];
    }
    if (t == 255) g_bsum[blockIdx.x] = sh[255];
}

// ------ scan pass 2+3 merged: block reduces its chunk prefix, finalizes
//        offsets/cursors, computes dinv & xs4, zeroes pool/cnt.
__global__ void __launch_bounds__(256) k_scan23(const float* __restrict__ x) {
    __shared__ int red[256];
    int t = threadIdx.x;
    int chunk = blockIdx.x >> 2;           // 4 blocks of 256 per 1024-chunk
    int part = 0;
    for (int j = t; j < chunk; j += 256) part += g_bsum[j];
    red[t] = part;
    __syncthreads();
    for (int o = 128; o; o >>= 1) {
        if (t < o) red[t] += red[t + o];
        __syncthreads();
    }
    int pref = red[0];

    int i = blockIdx.x * 256 + t;
    if (i < NN) {
        int o = g_off[i] + pref;
        g_off[i] = o;
        g_cur[i] = o;
        float d = rsqrtf((float)g_icnt[i] + 1.0f);
        g_dinv[i] = d;
        ((float4*)g_xs4)[i] =
            make_float4(d * x[i * 3 + 0], d * x[i * 3 + 1], d * x[i * 3 + 2], d);
    }
    if (i < NG * H2C) g_pool[i] = 0.f;
    if (i < NG)       g_cnt[i]  = 0.f;
}

// -------------------------------- CSR fill
__global__ void k_fill(const int* __restrict__ src, const int* __restrict__ dst) {
    int e = blockIdx.x * blockDim.x + threadIdx.x;
    if (e >= NE) return;
    int d = dst[e];
    int pos = atomicAdd(&g_cur[d], 1);
    g_csrc[pos] = src[e];
}

// ------- layer 1 fused gather + dense (warp per node), fp16 output
__global__ void __launch_bounds__(128) k_l1g(const float* __restrict__ W1,
                                             const float* __restrict__ b1) {
    int warp = threadIdx.x >> 5;
    int lane = threadIdx.x & 31;
    int node = blockIdx.x * 4 + warp;
    if (node >= NN) return;

    int beg = g_off[node];
    int cnt = g_icnt[node];
    float sx = 0.f, sy = 0.f, sz = 0.f;
    for (int j = lane; j < cnt; j += 32) {
        int s = g_csrc[beg + j];
        float4 v = ((const float4*)g_xs4)[s];
        sx += v.x; sy += v.y; sz += v.z;
    }
#pragma unroll
    for (int o = 16; o; o >>= 1) {
        sx += __shfl_xor_sync(0xffffffffu, sx, o);
        sy += __shfl_xor_sync(0xffffffffu, sy, o);
        sz += __shfl_xor_sync(0xffffffffu, sz, o);
    }
    float4 self = ((const float4*)g_xs4)[node];
    float d = self.w;
    float a0 = d * (sx + self.x);
    float a1 = d * (sy + self.y);
    float a2 = d * (sz + self.z);

    int f = lane * 2;
    float v0 = a0 * __ldg(&W1[f])       + a1 * __ldg(&W1[64 + f])
             + a2 * __ldg(&W1[128 + f])   + __ldg(&b1[f]);
    float v1 = a0 * __ldg(&W1[f + 1])   + a1 * __ldg(&W1[64 + f + 1])
             + a2 * __ldg(&W1[128 + f + 1]) + __ldg(&b1[f + 1]);
    g_h1h[node * 32 + lane] =
        __floats2half2_rn(d * fmaxf(v0, 0.f), d * fmaxf(v1, 0.f));
}

// ------- layer 2 edge aggregation via CSR (warp per node, fp32 acc, half2 out)
__global__ void __launch_bounds__(128) k_eh() {
    int warp = threadIdx.x >> 5;
    int lane = threadIdx.x & 31;
    int node = blockIdx.x * 4 + warp;
    if (node >= NN) return;

    int beg = g_off[node];
    int cnt = g_icnt[node];
    const __half2* H = g_h1h;

    float2 accA = __half22float2(H[node * 32 + lane]);  // self term
    float2 accB = make_float2(0.f, 0.f);

    int j = 0;
#pragma unroll 2
    for (; j + 2 <= cnt; j += 2) {
        int s0 = g_csrc[beg + j];
        int s1 = g_csrc[beg + j + 1];
        float2 v0 = __half22float2(H[s0 * 32 + lane]);
        float2 v1 = __half22float2(H[s1 * 32 + lane]);
        accA.x += v0.x; accA.y += v0.y;
        accB.x += v1.x; accB.y += v1.y;
    }
    if (j < cnt) {
        int s = g_csrc[beg + j];
        float2 v = __half22float2(H[s * 32 + lane]);
        accA.x += v.x; accA.y += v.y;
    }
    float d = g_dinv[node];
    g_aggh2[node * 32 + lane] =
        __floats2half2_rn(d * (accA.x + accB.x), d * (accA.y + accB.y));
}

// ---- layer-2 dense via tensor cores + fused mean-pool
// 3 warps/block, warp strides over 16-node tiles (amortizes W2 staging).
#define L2PAD 130
__global__ void __launch_bounds__(96)
k_l2t(const float* __restrict__ W2, const float* __restrict__ b2,
      const int* __restrict__ batch) {
    __shared__ __half2 sB[128 * 33];          // W2 fragments: pair(k,k+1) per col
    __shared__ float   sC[3][16 * L2PAD];     // per-warp C staging

    int tid = threadIdx.x;
    // COALESCED staging: consecutive threads read consecutive n within a W2 row
    for (int idx = tid; idx < 128 * 32; idx += 96) {
        int j = idx >> 7;          // k-pair 0..31
        int n = idx & 127;         // output column
        sB[n * 33 + j] =
            __floats2half2_rn(W2[(2 * j) * H2C + n], W2[(2 * j + 1) * H2C + n]);
    }
    __syncthreads();

    int warp = tid >> 5, lane = tid & 31;
    int g = lane >> 2, t = lane & 3;
    float bias0 = __ldg(&b2[lane]);
    float bias1 = __ldg(&b2[lane + 32]);
    float bias2 = __ldg(&b2[lane + 64]);
    float bias3 = __ldg(&b2[lane + 96]);
    float* myC = sC[warp];
    const unsigned* A = (const unsigned*)g_aggh2;
    int wstride = gridDim.x * 3;

    for (int tile = blockIdx.x * 3 + warp; tile < NTILES; tile += wstride) {
        int node0 = tile * 16;

        // A fragments: 4 k-steps × 4 b32 regs
        unsigned a[4][4];
        {
            int r0 = (node0 + g) * 32, r1 = (node0 + g + 8) * 32;
#pragma unroll
            for (int kk = 0; kk < 4; kk++) {
                a[kk][0] = A[r0 + kk * 8 + t];
                a[kk][1] = A[r1 + kk * 8 + t];
                a[kk][2] = A[r0 + kk * 8 + t + 4];
                a[kk][3] = A[r1 + kk * 8 + t + 4];
            }
        }
        __syncwarp();   // sC WAR: previous iteration's reads done before rewrite
#pragma unroll
        for (int nt = 0; nt < 16; nt++) {
            float c0 = 0.f, c1 = 0.f, c2 = 0.f, c3 = 0.f;
            int n = nt * 8 + g;
#pragma unroll
            for (int kk = 0; kk < 4; kk++) {
                unsigned b0 = *(const unsigned*)&sB[n * 33 + kk * 8 + t];
                unsigned b1 = *(const unsigned*)&sB[n * 33 + kk * 8 + t + 4];
                asm volatile(
                    "mma.sync.aligned.m16n8k16.row.col.f32.f16.f16.f32 "
                    "{%0,%1,%2,%3}, {%4,%5,%6,%7}, {%8,%9}, {%0,%1,%2,%3};"
                    : "+f"(c0), "+f"(c1), "+f"(c2), "+f"(c3)
                    : "r"(a[kk][0]), "r"(a[kk][1]), "r"(a[kk][2]), "r"(a[kk][3]),
                      "r"(b0), "r"(b1));
            }
            int col = nt * 8 + t * 2;
            *(float2*)&myC[g * L2PAD + col]       = make_float2(c0, c1);
            *(float2*)&myC[(g + 8) * L2PAD + col] = make_float2(c2, c3);
        }
        __syncwarp();

        // pooling epilogue: lane owns cols {lane,+32,+64,+96}; run-flush on batch
        float p0 = 0.f, p1 = 0.f, p2 = 0.f, p3 = 0.f, cntacc = 0.f;
        int cur_g = batch[node0];
#pragma unroll
        for (int r = 0; r < 16; r++) {
            int gid = batch[node0 + r];
            if (gid != cur_g) {
                red_add_f(&g_pool[cur_g * H2C + lane],      p0);
                red_add_f(&g_pool[cur_g * H2C + lane + 32], p1);
                red_add_f(&g_pool[cur_g * H2C + lane + 64], p2);
                red_add_f(&g_pool[cur_g * H2C + lane + 96], p3);
                if (lane == 0) red_add_f(&g_cnt[cur_g], cntacc);
                p0 = p1 = p2 = p3 = 0.f; cntacc = 0.f; cur_g = gid;
            }
            const float* row = &myC[r * L2PAD];
            p0 += fmaxf(row[lane]      + bias0, 0.f);
            p1 += fmaxf(row[lane + 32] + bias1, 0.f);
            p2 += fmaxf(row[lane + 64] + bias2, 0.f);
            p3 += fmaxf(row[lane + 96] + bias3, 0.f);
            cntacc += 1.f;
        }
        red_add_f(&g_pool[cur_g * H2C + lane],      p0);
        red_add_f(&g_pool[cur_g * H2C + lane + 32], p1);
        red_add_f(&g_pool[cur_g * H2C + lane + 64], p2);
        red_add_f(&g_pool[cur_g * H2C + lane + 96], p3);
        if (lane == 0) red_add_f(&g_cnt[cur_g], cntacc);
    }
}

// ---------------------------------------- final: out = (pool/cnt)@Wfc + bfc
__global__ void k_out(const float* __restrict__ Wfc, const float* __restrict__ bfc,
                      float* __restrict__ out) {
    int t = blockIdx.x * blockDim.x + threadIdx.x;
    if (t >= NG * OUTC) return;
    int g = t >> 1, o = t & 1;
    float inv = 1.0f / fmaxf(g_cnt[g], 1.0f);
    float s = 0.f;
#pragma unroll
    for (int k = 0; k < H2C; k++)
        s = fmaf(g_pool[g * H2C + k], __ldg(&Wfc[k * OUTC + o]), s);
    out[t] = s * inv + __ldg(&bfc[o]);
}

extern "C" void kernel_launch(void* const* d_in, const int* in_sizes, int n_in,
                              void* d_out, int out_size) {
    const float* x   = (const float*)d_in[0];
    const int*   ei  = (const int*)d_in[1];   // [2, E] int32
    const int*   bat = (const int*)d_in[2];   // [N] int32
    const float* W1  = (const float*)d_in[3];
    const float* b1  = (const float*)d_in[4];
    const float* W2  = (const float*)d_in[5];
    const float* b2  = (const float*)d_in[6];
    const float* Wfc = (const float*)d_in[7];
    const float* bfc = (const float*)d_in[8];
    float*       out = (float*)d_out;

    const int* src = ei;
    const int* dst = ei + NE;

    const int T = 256;
    k_zero  <<<(NN / 4 + T - 1) / T, T>>>();
    k_count <<<(NE + T - 1) / T, T>>>(dst);
    k_scan1 <<<NBS, 256>>>();
    k_scan23<<<(NN + 255) / 256, 256>>>(x);
    k_fill  <<<(NE + T - 1) / T, T>>>(src, dst);
    k_l1g   <<<NN / 4, 128>>>(W1, b1);
    k_eh    <<<NN / 4, 128>>>();
    k_l2t   <<<740, 96>>>(W2, b2, bat);
    k_out   <<<(NG * OUTC + T - 1) / T, T>>>(Wfc, bfc, out);
}

// round 10
// speedup vs baseline: 1.5001x; 1.0254x over previous
#include <cuda_runtime.h>
#include <cuda_fp16.h>
#include <cuda_bf16.h>

#define NN 100000
#define NE 1600000
#define NG 512
#define H1C 64
#define H2C 128
#define OUTC 2
#define NBS 98          // ceil(NN / 1024) scan blocks
#define NTILES 6250     // NN / 16

// ---------------- scratch (__device__ globals) ----------------
__device__ __align__(16) int     g_icnt[NN];        // in-degree
__device__ __align__(16) int     g_off [NN];        // CSR exclusive offsets
__device__ __align__(16) int     g_cur [NN];        // scatter cursors
__device__ __align__(16) int     g_bsum[128];       // scan block sums
__device__ __align__(16) int     g_csrc[NE];        // CSR: src per slot
__device__ __align__(16) float   g_dinv[NN];
__device__ __align__(16) float   g_xs4 [NN * 4];    // {d*x0, d*x1, d*x2, d}
__device__ __align__(16) float   g_aggx4[NN * 4];   // layer-1 aggregate (seeded self)
__device__ __align__(16) __half2 g_h1h [NN * 32];   // fp16 dinv-scaled relu(layer1)
__device__ __align__(16) __half2 g_aggh2[NN * 32];  // fp16 layer-2 aggregate
__device__ __align__(16) float   g_pool[NG * H2C];
__device__ __align__(16) float   g_cnt [NG];

__device__ __forceinline__ void red_add_f(float* addr, float v) {
    asm volatile("red.global.add.f32 [%0], %1;" :: "l"(addr), "f"(v) : "memory");
}
__device__ __forceinline__ void red_add_v4(float* addr, float4 v) {
    asm volatile("red.global.add.v4.f32 [%0], {%1,%2,%3,%4};"
                 :: "l"(addr), "f"(v.x), "f"(v.y), "f"(v.z), "f"(v.w)
                 : "memory");
}

// -------------------------------- zero in-degree counters
__global__ void k_zero() {
    int i = blockIdx.x * blockDim.x + threadIdx.x;
    if (i < NN / 4) ((int4*)g_icnt)[i] = make_int4(0, 0, 0, 0);
}

// -------------------------------- in-degree count (4 edges/thread)
__global__ void k_count(const int* __restrict__ dst) {
    int i = blockIdx.x * blockDim.x + threadIdx.x;
    if (i >= NE / 4) return;
    int4 d4 = ((const int4*)dst)[i];
    atomicAdd(&g_icnt[d4.x], 1);
    atomicAdd(&g_icnt[d4.y], 1);
    atomicAdd(&g_icnt[d4.z], 1);
    atomicAdd(&g_icnt[d4.w], 1);
}

// -------------------------------- scan pass 1: per-1024 chunks
__global__ void __launch_bounds__(256) k_scan1() {
    __shared__ int sh[256];
    int base = blockIdx.x * 1024;
    int t = threadIdx.x;
    int v[4], s = 0;
#pragma unroll
    for (int j = 0; j < 4; j++) {
        int idx = base + t * 4 + j;
        v[j] = (idx < NN) ? g_icnt[idx] : 0;
        s += v[j];
    }
    sh[t] = s;
    __syncthreads();
    for (int o = 1; o < 256; o <<= 1) {
        int x = (t >= o) ? sh[t - o] : 0;
        __syncthreads();
        sh[t] += x;
        __syncthreads();
    }
    int run = sh[t] - s;
#pragma unroll
    for (int j = 0; j < 4; j++) {
        int idx = base + t * 4 + j;
        if (idx < NN) g_off[idx] = run;
        run += v[j];
    }
    if (t == 255) g_bsum[blockIdx.x] = sh[255];
}

// ------ scan pass 2+3 merged: finalize offsets/cursors, dinv, xs4 (+seed aggx4),
//        zero pool/cnt.
__global__ void __launch_bounds__(256) k_scan23(const float* __restrict__ x) {
    __shared__ int red[256];
    int t = threadIdx.x;
    int chunk = blockIdx.x >> 2;           // 4 blocks of 256 per 1024-chunk
    int part = 0;
    for (int j = t; j < chunk; j += 256) part += g_bsum[j];
    red[t] = part;
    __syncthreads();
    for (int o = 128; o; o >>= 1) {
        if (t < o) red[t] += red[t + o];
        __syncthreads();
    }
    int pref = red[0];

    int i = blockIdx.x * 256 + t;
    if (i < NN) {
        int o = g_off[i] + pref;
        g_off[i] = o;
        g_cur[i] = o;
        float d = rsqrtf((float)g_icnt[i] + 1.0f);
        g_dinv[i] = d;
        float4 v = make_float4(d * x[i * 3 + 0], d * x[i * 3 + 1],
                               d * x[i * 3 + 2], d);
        ((float4*)g_xs4)[i]   = v;
        ((float4*)g_aggx4)[i] = v;   // self-loop seed for layer-1 aggregate
    }
    if (i < NG * H2C) g_pool[i] = 0.f;
    if (i < NG)       g_cnt[i]  = 0.f;
}

// ------------- CSR fill + fused layer-1 edge aggregation (indices reused)
__global__ void k_fill(const int* __restrict__ src, const int* __restrict__ dst) {
    int e = blockIdx.x * blockDim.x + threadIdx.x;
    if (e >= NE) return;
    int d = dst[e];
    int s = src[e];
    int pos = atomicAdd(&g_cur[d], 1);
    g_csrc[pos] = s;
    float4 v = ((const float4*)g_xs4)[s];
    red_add_v4(&g_aggx4[d * 4], v);
}

// ------- layer 1 dense: h1h = fp16( d * relu( (d*aggx) @ W1 + b1 ) )
__global__ void k_l1(const float* __restrict__ W1, const float* __restrict__ b1) {
    int t = blockIdx.x * blockDim.x + threadIdx.x;
    if (t >= NN * 32) return;
    int i = t >> 5, l = t & 31, f = l * 2;
    float4 a4 = __ldg((const float4*)&g_aggx4[i * 4]);
    float d = g_dinv[i];
    float a0 = d * a4.x, a1 = d * a4.y, a2 = d * a4.z;
    float v0 = a0 * __ldg(&W1[f])       + a1 * __ldg(&W1[64 + f])
             + a2 * __ldg(&W1[128 + f])   + __ldg(&b1[f]);
    float v1 = a0 * __ldg(&W1[f + 1])   + a1 * __ldg(&W1[64 + f + 1])
             + a2 * __ldg(&W1[128 + f + 1]) + __ldg(&b1[f + 1]);
    g_h1h[i * 32 + l] =
        __floats2half2_rn(d * fmaxf(v0, 0.f), d * fmaxf(v1, 0.f));
}

// ------- layer 2 edge aggregation via CSR (warp per node, 4 fp32 accumulators)
__global__ void __launch_bounds__(128) k_eh() {
    int warp = threadIdx.x >> 5;
    int lane = threadIdx.x & 31;
    int node = blockIdx.x * 4 + warp;
    if (node >= NN) return;

    int beg = g_off[node];
    int cnt = g_icnt[node];
    const __half2* H = g_h1h;

    float2 accA = __half22float2(H[node * 32 + lane]);  // self term
    float2 accB = make_float2(0.f, 0.f);
    float2 accC = make_float2(0.f, 0.f);
    float2 accD = make_float2(0.f, 0.f);

    int j = 0;
    for (; j + 4 <= cnt; j += 4) {
        int s0 = g_csrc[beg + j];
        int s1 = g_csrc[beg + j + 1];
        int s2 = g_csrc[beg + j + 2];
        int s3 = g_csrc[beg + j + 3];
        float2 v0 = __half22float2(H[s0 * 32 + lane]);
        float2 v1 = __half22float2(H[s1 * 32 + lane]);
        float2 v2 = __half22float2(H[s2 * 32 + lane]);
        float2 v3 = __half22float2(H[s3 * 32 + lane]);
        accA.x += v0.x; accA.y += v0.y;
        accB.x += v1.x; accB.y += v1.y;
        accC.x += v2.x; accC.y += v2.y;
        accD.x += v3.x; accD.y += v3.y;
    }
    for (; j < cnt; j++) {
        int s = g_csrc[beg + j];
        float2 v = __half22float2(H[s * 32 + lane]);
        accA.x += v.x; accA.y += v.y;
    }
    float d = g_dinv[node];
    g_aggh2[node * 32 + lane] = __floats2half2_rn(
        d * ((accA.x + accB.x) + (accC.x + accD.x)),
        d * ((accA.y + accB.y) + (accC.y + accD.y)));
}

// ---- layer-2 dense via tensor cores + fused mean-pool (3 warps/block, striding)
#define L2PAD 130
__global__ void __launch_bounds__(96)
k_l2t(const float* __restrict__ W2, const float* __restrict__ b2,
      const int* __restrict__ batch) {
    __shared__ __half2 sB[128 * 33];          // W2 fragments: pair(k,k+1) per col
    __shared__ float   sC[3][16 * L2PAD];     // per-warp C staging

    int tid = threadIdx.x;
    for (int idx = tid; idx < 128 * 32; idx += 96) {
        int j = idx >> 7;          // k-pair 0..31
        int n = idx & 127;         // output column
        sB[n * 33 + j] =
            __floats2half2_rn(W2[(2 * j) * H2C + n], W2[(2 * j + 1) * H2C + n]);
    }
    __syncthreads();

    int warp = tid >> 5, lane = tid & 31;
    int g = lane >> 2, t = lane & 3;
    float bias0 = __ldg(&b2[lane]);
    float bias1 = __ldg(&b2[lane + 32]);
    float bias2 = __ldg(&b2[lane + 64]);
    float bias3 = __ldg(&b2[lane + 96]);
    float* myC = sC[warp];
    const unsigned* A = (const unsigned*)g_aggh2;
    int wstride = gridDim.x * 3;

    for (int tile = blockIdx.x * 3 + warp; tile < NTILES; tile += wstride) {
        int node0 = tile * 16;

        unsigned a[4][4];
        {
            int r0 = (node0 + g) * 32, r1 = (node0 + g + 8) * 32;
#pragma unroll
            for (int kk = 0; kk < 4; kk++) {
                a[kk][0] = A[r0 + kk * 8 + t];
                a[kk][1] = A[r1 + kk * 8 + t];
                a[kk][2] = A[r0 + kk * 8 + t + 4];
                a[kk][3] = A[r1 + kk * 8 + t + 4];
            }
        }
        __syncwarp();   // sC WAR across tile iterations
#pragma unroll
        for (int nt = 0; nt < 16; nt++) {
            float c0 = 0.f, c1 = 0.f, c2 = 0.f, c3 = 0.f;
            int n = nt * 8 + g;
#pragma unroll
            for (int kk = 0; kk < 4; kk++) {
                unsigned b0 = *(const unsigned*)&sB[n * 33 + kk * 8 + t];
                unsigned b1 = *(const unsigned*)&sB[n * 33 + kk * 8 + t + 4];
                asm volatile(
                    "mma.sync.aligned.m16n8k16.row.col.f32.f16.f16.f32 "
                    "{%0,%1,%2,%3}, {%4,%5,%6,%7}, {%8,%9}, {%0,%1,%2,%3};"
                    : "+f"(c0), "+f"(c1), "+f"(c2), "+f"(c3)
                    : "r"(a[kk][0]), "r"(a[kk][1]), "r"(a[kk][2]), "r"(a[kk][3]),
                      "r"(b0), "r"(b1));
            }
            int col = nt * 8 + t * 2;
            *(float2*)&myC[g * L2PAD + col]       = make_float2(c0, c1);
            *(float2*)&myC[(g + 8) * L2PAD + col] = make_float2(c2, c3);
        }
        __syncwarp();

        float p0 = 0.f, p1 = 0.f, p2 = 0.f, p3 = 0.f, cntacc = 0.f;
        int cur_g = batch[node0];
#pragma unroll
        for (int r = 0; r < 16; r++) {
            int gid = batch[node0 + r];
            if (gid != cur_g) {
                red_add_f(&g_pool[cur_g * H2C + lane],      p0);
                red_add_f(&g_pool[cur_g * H2C + lane + 32], p1);
                red_add_f(&g_pool[cur_g * H2C + lane + 64], p2);
                red_add_f(&g_pool[cur_g * H2C + lane + 96], p3);
                if (lane == 0) red_add_f(&g_cnt[cur_g], cntacc);
                p0 = p1 = p2 = p3 = 0.f; cntacc = 0.f; cur_g = gid;
            }
            const float* row = &myC[r * L2PAD];
            p0 += fmaxf(row[lane]      + bias0, 0.f);
            p1 += fmaxf(row[lane + 32] + bias1, 0.f);
            p2 += fmaxf(row[lane + 64] + bias2, 0.f);
            p3 += fmaxf(row[lane + 96] + bias3, 0.f);
            cntacc += 1.f;
        }
        red_add_f(&g_pool[cur_g * H2C + lane],      p0);
        red_add_f(&g_pool[cur_g * H2C + lane + 32], p1);
        red_add_f(&g_pool[cur_g * H2C + lane + 64], p2);
        red_add_f(&g_pool[cur_g * H2C + lane + 96], p3);
        if (lane == 0) red_add_f(&g_cnt[cur_g], cntacc);
    }
}

// ---------------------------------------- final: out = (pool/cnt)@Wfc + bfc
__global__ void k_out(const float* __restrict__ Wfc, const float* __restrict__ bfc,
                      float* __restrict__ out) {
    int t = blockIdx.x * blockDim.x + threadIdx.x;
    if (t >= NG * OUTC) return;
    int g = t >> 1, o = t & 1;
    float inv = 1.0f / fmaxf(g_cnt[g], 1.0f);
    float s = 0.f;
#pragma unroll
    for (int k = 0; k < H2C; k++)
        s = fmaf(g_pool[g * H2C + k], __ldg(&Wfc[k * OUTC + o]), s);
    out[t] = s * inv + __ldg(&bfc[o]);
}

extern "C" void kernel_launch(void* const* d_in, const int* in_sizes, int n_in,
                              void* d_out, int out_size) {
    const float* x   = (const float*)d_in[0];
    const int*   ei  = (const int*)d_in[1];   // [2, E] int32
    const int*   bat = (const int*)d_in[2];   // [N] int32
    const float* W1  = (const float*)d_in[3];
    const float* b1  = (const float*)d_in[4];
    const float* W2  = (const float*)d_in[5];
    const float* b2  = (const float*)d_in[6];
    const float* Wfc = (const float*)d_in[7];
    const float* bfc = (const float*)d_in[8];
    float*       out = (float*)d_out;

    const int* src = ei;
    const int* dst = ei + NE;

    const int T = 256;
    k_zero  <<<(NN / 4 + T - 1) / T, T>>>();
    k_count <<<(NE / 4 + T - 1) / T, T>>>(dst);
    k_scan1 <<<NBS, 256>>>();
    k_scan23<<<(NN + 255) / 256, 256>>>(x);
    k_fill  <<<(NE + T - 1) / T, T>>>(src, dst);
    k_l1    <<<(NN * 32 + T - 1) / T, T>>>(W1, b1);
    k_eh    <<<NN / 4, 128>>>();
    k_l2t   <<<740, 96>>>(W2, b2, bat);
    k_out   <<<(NG * OUTC + T - 1) / T, T>>>(Wfc, bfc, out);
}